// round 3
// baseline (speedup 1.0000x reference)
#include <cuda_runtime.h>
#include <math.h>

#define B_   2
#define T_   2048
#define DIM_ 4096
#define NH   32
#define NKV  8
#define HD   128
#define RG   (NH / NKV)

#define QSCALE 0.08838834764831843f  // 1/sqrt(128)

// ---------------- scratch (allocation-free: __device__ globals) ----------------
__device__ float g_q[(size_t)B_ * NH  * T_ * HD];   // [B,H,T,hd], pre-scaled
__device__ float g_k[(size_t)B_ * NKV * T_ * HD];   // [B,KV,T,hd]
__device__ float g_v[(size_t)B_ * NKV * T_ * HD];   // [B,KV,T,hd]
__device__ float g_o[(size_t)B_ * T_ * DIM_];       // [B,T,H*hd]

// ---------------- tiled fp32 GEMM:  C[M,N] = A[M,K] @ W[N,K]^T ----------------
// MODE 0: W = concat(Wq rows [0,4096), Wkv rows [0,2048)); scatter epilogue into
//         g_q (scaled), g_k, g_v.
// MODE 1: plain C[m*N+n] store (O projection).
#define BM 128
#define BN 128
#define BK 16
#define TM 8
#define TN 8

template <int MODE>
__global__ void __launch_bounds__(256)
gemm_kernel(const float* __restrict__ A,
            const float* __restrict__ W0,     // Wq (MODE 0) or Wo (MODE 1)
            const float* __restrict__ W1,     // Wkv (MODE 0) or unused
            float* __restrict__ outQ,         // g_q (MODE 0) or C (MODE 1)
            float* __restrict__ outK,
            float* __restrict__ outV,
            int M, int N, int K)
{
    __shared__ float As[BK][BM];
    __shared__ float Bs[BK][BN];

    const int tid = threadIdx.x;
    const int m0  = blockIdx.y * BM;
    const int n0  = blockIdx.x * BN;
    const int tx  = tid & 15;        // 0..15  -> N direction
    const int ty  = tid >> 4;        // 0..15  -> M direction

    float acc[TM][TN];
#pragma unroll
    for (int i = 0; i < TM; i++)
#pragma unroll
        for (int j = 0; j < TN; j++) acc[i][j] = 0.f;

    for (int k0 = 0; k0 < K; k0 += BK) {
        // cooperative loads: 512 float4 slots per tile; 2 per thread
#pragma unroll
        for (int u = 0; u < 2; u++) {
            const int s   = tid * 2 + u;
            const int row = s >> 2;          // 0..127
            const int kv  = (s & 3) * 4;     // 0,4,8,12

            float4 a4 = *(const float4*)(A + (size_t)(m0 + row) * K + k0 + kv);
            As[kv + 0][row] = a4.x;
            As[kv + 1][row] = a4.y;
            As[kv + 2][row] = a4.z;
            As[kv + 3][row] = a4.w;

            const int n = n0 + row;
            const float* wr;
            if (MODE == 0 && n >= DIM_) wr = W1 + (size_t)(n - DIM_) * K;
            else                        wr = W0 + (size_t)n * K;
            float4 b4 = *(const float4*)(wr + k0 + kv);
            Bs[kv + 0][row] = b4.x;
            Bs[kv + 1][row] = b4.y;
            Bs[kv + 2][row] = b4.z;
            Bs[kv + 3][row] = b4.w;
        }
        __syncthreads();

#pragma unroll
        for (int k = 0; k < BK; k++) {
            float4 a0 = *(const float4*)&As[k][ty * TM];
            float4 a1 = *(const float4*)&As[k][ty * TM + 4];
            float4 b0 = *(const float4*)&Bs[k][tx * TN];
            float4 b1 = *(const float4*)&Bs[k][tx * TN + 4];
            float a[TM] = {a0.x, a0.y, a0.z, a0.w, a1.x, a1.y, a1.z, a1.w};
            float b[TN] = {b0.x, b0.y, b0.z, b0.w, b1.x, b1.y, b1.z, b1.w};
#pragma unroll
            for (int i = 0; i < TM; i++)
#pragma unroll
                for (int j = 0; j < TN; j++)
                    acc[i][j] = fmaf(a[i], b[j], acc[i][j]);
        }
        __syncthreads();
    }

    // epilogue
#pragma unroll
    for (int i = 0; i < TM; i++) {
        const int m  = m0 + ty * TM + i;
        const int bb = m >> 11;          // /T_ (2048)
        const int t  = m & (T_ - 1);
#pragma unroll
        for (int j = 0; j < TN; j++) {
            const int n = n0 + tx * TN + j;
            const float v = acc[i][j];
            if (MODE == 1) {
                outQ[(size_t)m * N + n] = v;
            } else {
                if (n < DIM_) {                       // Q
                    const int h = n >> 7, d = n & 127;
                    outQ[(((size_t)bb * NH + h) * T_ + t) * HD + d] = v * QSCALE;
                } else {
                    const int cc = n - DIM_;
                    const int d = cc & 127;
                    if (cc < NKV * HD) {              // K
                        outK[(((size_t)bb * NKV + (cc >> 7)) * T_ + t) * HD + d] = v;
                    } else {                          // V
                        const int c2 = cc - NKV * HD;
                        outV[(((size_t)bb * NKV + (c2 >> 7)) * T_ + t) * HD + d] = v;
                    }
                }
            }
        }
    }
}

// ---------------- flash attention, fp32, causal, GQA ----------------
// Block: 256 threads; tile Br=64 queries x Bc=64 keys, hd=128.
// Thread mapping: r = tid>>2 (row 0..63), c = tid&3.
//   S phase: thread owns 16 score columns [c*16, c*16+16)
//   PV phase: thread owns 32 out dims    [c*32, c*32+32)
#define BR 64
#define BC 64
#define FLASH_SMEM ((3 * BR * HD + BR * BC) * (int)sizeof(float))  // 112 KB + P

__global__ void __launch_bounds__(256)
flash_kernel(const float* __restrict__ Q, const float* __restrict__ Kg,
             const float* __restrict__ Vg, float* __restrict__ O)
{
    extern __shared__ float sm[];
    float* Qs = sm;                  // [64][128]
    float* Ks = Qs + BR * HD;        // [64][128]
    float* Vs = Ks + BC * HD;        // [64][128]
    float* Ps = Vs + BC * HD;        // [64][64]

    const int qt = blockIdx.x;
    const int h  = blockIdx.y;
    const int b  = blockIdx.z;
    const int g  = h / RG;
    const int tid = threadIdx.x;

    const float* Qbase = Q  + (((size_t)b * NH  + h) * T_ + (size_t)qt * BR) * HD;
    const float* Kbase = Kg + (((size_t)b * NKV + g) * T_) * HD;
    const float* Vbase = Vg + (((size_t)b * NKV + g) * T_) * HD;

    // Q tile is a contiguous 64*128 chunk
    for (int i = tid; i < BR * HD / 4; i += 256)
        ((float4*)Qs)[i] = ((const float4*)Qbase)[i];

    const int r   = tid >> 2;
    const int c   = tid & 3;
    const int jj0 = c * 16;
    const int d0  = c * 32;

    float m_i = -1e30f, l_i = 0.f;
    float acc[32];
#pragma unroll
    for (int i = 0; i < 32; i++) acc[i] = 0.f;

    for (int kt = 0; kt <= qt; kt++) {
        __syncthreads();   // protect K/V/P from previous iteration readers
        const float4* Ksrc = (const float4*)(Kbase + (size_t)kt * BC * HD);
        const float4* Vsrc = (const float4*)(Vbase + (size_t)kt * BC * HD);
        for (int i = tid; i < BC * HD / 4; i += 256) {
            ((float4*)Ks)[i] = Ksrc[i];
            ((float4*)Vs)[i] = Vsrc[i];
        }
        __syncthreads();

        // S = Q @ K^T  (Q pre-scaled)
        float s[16];
#pragma unroll
        for (int j = 0; j < 16; j++) s[j] = 0.f;
        const float4* qrow = (const float4*)(Qs + r * HD);
#pragma unroll 4
        for (int d4 = 0; d4 < HD / 4; d4++) {
            float4 q4 = qrow[d4];
#pragma unroll
            for (int j = 0; j < 16; j++) {
                float4 k4 = ((const float4*)(Ks + (jj0 + j) * HD))[d4];
                s[j] += q4.x * k4.x + q4.y * k4.y + q4.z * k4.z + q4.w * k4.w;
            }
        }

        if (kt == qt) {
#pragma unroll
            for (int j = 0; j < 16; j++)
                if (jj0 + j > r) s[j] = -1e30f;
        }

        // online softmax (4 lanes per row, reduce with shfl)
        float mt = s[0];
#pragma unroll
        for (int j = 1; j < 16; j++) mt = fmaxf(mt, s[j]);
        mt = fmaxf(mt, __shfl_xor_sync(0xffffffffu, mt, 1));
        mt = fmaxf(mt, __shfl_xor_sync(0xffffffffu, mt, 2));
        const float mnew = fmaxf(m_i, mt);

        float lt = 0.f;
#pragma unroll
        for (int j = 0; j < 16; j++) {
            s[j] = __expf(s[j] - mnew);
            lt += s[j];
        }
        lt += __shfl_xor_sync(0xffffffffu, lt, 1);
        lt += __shfl_xor_sync(0xffffffffu, lt, 2);

        const float alpha = __expf(m_i - mnew);
        l_i = l_i * alpha + lt;
        m_i = mnew;
#pragma unroll
        for (int i = 0; i < 32; i++) acc[i] *= alpha;

#pragma unroll
        for (int j = 0; j < 16; j++) Ps[r * BC + jj0 + j] = s[j];
        __syncthreads();

        // acc += P @ V
#pragma unroll 4
        for (int j = 0; j < BC; j++) {
            const float p = Ps[r * BC + j];
            const float4* vrow = (const float4*)(Vs + j * HD + d0);
#pragma unroll
            for (int dd = 0; dd < 8; dd++) {
                float4 v4 = vrow[dd];
                acc[dd * 4 + 0] = fmaf(p, v4.x, acc[dd * 4 + 0]);
                acc[dd * 4 + 1] = fmaf(p, v4.y, acc[dd * 4 + 1]);
                acc[dd * 4 + 2] = fmaf(p, v4.z, acc[dd * 4 + 2]);
                acc[dd * 4 + 3] = fmaf(p, v4.w, acc[dd * 4 + 3]);
            }
        }
    }

    const float inv_l = 1.f / l_i;
    float* Od = O + ((size_t)(b * T_ + qt * BR + r)) * DIM_ + h * HD + d0;
#pragma unroll
    for (int dd = 0; dd < 8; dd++) {
        float4 o4;
        o4.x = acc[dd * 4 + 0] * inv_l;
        o4.y = acc[dd * 4 + 1] * inv_l;
        o4.z = acc[dd * 4 + 2] * inv_l;
        o4.w = acc[dd * 4 + 3] * inv_l;
        ((float4*)Od)[dd] = o4;
    }
}

// ---------------- launch ----------------
extern "C" void kernel_launch(void* const* d_in, const int* in_sizes, int n_in,
                              void* d_out, int out_size)
{
    const float* x   = (const float*)d_in[0];
    const float* Wq  = (const float*)d_in[1];
    const float* Wkv = (const float*)d_in[2];
    const float* Wo  = (const float*)d_in[3];
    float* out = (float*)d_out;

    float *pq, *pk, *pv, *po;
    cudaGetSymbolAddress((void**)&pq, g_q);
    cudaGetSymbolAddress((void**)&pk, g_k);
    cudaGetSymbolAddress((void**)&pv, g_v);
    cudaGetSymbolAddress((void**)&po, g_o);

    // 1) fused QKV projection: [4096,4096] @ [6144,4096]^T, scatter epilogue
    {
        dim3 grid((DIM_ + 2 * NKV * HD) / BN, (B_ * T_) / BM);  // 48 x 32
        gemm_kernel<0><<<grid, 256>>>(x, Wq, Wkv, pq, pk, pv,
                                      B_ * T_, DIM_ + 2 * NKV * HD, DIM_);
    }

    // 2) causal GQA flash attention
    {
        cudaFuncSetAttribute(flash_kernel,
                             cudaFuncAttributeMaxDynamicSharedMemorySize, FLASH_SMEM);
        dim3 grid(T_ / BR, NH, B_);  // 32 x 32 x 2
        flash_kernel<<<grid, 256, FLASH_SMEM>>>(pq, pk, pv, po);
    }

    // 3) output projection: [4096,4096] @ [4096,4096]^T
    {
        dim3 grid(DIM_ / BN, (B_ * T_) / BM);  // 32 x 32
        gemm_kernel<1><<<grid, 256>>>(po, Wo, nullptr, out, nullptr, nullptr,
                                      B_ * T_, DIM_, DIM_);
    }
}

// round 4
// speedup vs baseline: 1.2713x; 1.2713x over previous
#include <cuda_runtime.h>
#include <cuda_bf16.h>
#include <math.h>
#include <stdint.h>

#define B_   2
#define T_   2048
#define DIM_ 4096
#define NH   32
#define NKV  8
#define HD   128
#define RG   (NH / NKV)
#define K3   (3 * DIM_)          // 12288, triple-expanded K

#define QSCALE 0.08838834764831843f  // 1/sqrt(128)

// ---------------- scratch (allocation-free: __device__ globals) ----------------
__device__ float g_q[(size_t)B_ * NH  * T_ * HD];   // [B,H,T,hd], pre-scaled
__device__ float g_k[(size_t)B_ * NKV * T_ * HD];   // [B,KV,T,hd]
__device__ float g_v[(size_t)B_ * NKV * T_ * HD];   // [B,KV,T,hd]
__device__ float g_o[(size_t)B_ * T_ * DIM_];       // [B,T,H*hd]

// triple-expanded bf16 operands
__device__ __nv_bfloat16 g_x3 [(size_t)(B_*T_) * K3];           // activations x
__device__ __nv_bfloat16 g_w13[(size_t)(DIM_ + 2*NKV*HD) * K3]; // Wq (4096 rows) ++ Wkv (2048 rows)
__device__ __nv_bfloat16 g_o3 [(size_t)(B_*T_) * K3];           // attention output
__device__ __nv_bfloat16 g_wo3[(size_t)DIM_ * K3];              // Wo

// ---------------- fp32 -> (hi,lo,hi)/(hi,hi,lo) bf16 expansion ----------------
// ACT pattern: (hi, lo, hi).  WGT pattern: (hi, hi, lo).
// Per original k: act*wgt over the 3 slots = hi_a*hi_w + lo_a*hi_w + hi_a*lo_w ~= a*w (fp32-accurate).
template <bool ACT>
__global__ void __launch_bounds__(256)
conv3_kernel(const float* __restrict__ in, __nv_bfloat16* __restrict__ out, int n8)
{
    int i = blockIdx.x * blockDim.x + threadIdx.x;
    if (i >= n8) return;
    float4 f0 = ((const float4*)in)[(size_t)i * 2];
    float4 f1 = ((const float4*)in)[(size_t)i * 2 + 1];
    float v[8] = {f0.x, f0.y, f0.z, f0.w, f1.x, f1.y, f1.z, f1.w};
    __align__(16) __nv_bfloat16 o[24];
#pragma unroll
    for (int j = 0; j < 8; j++) {
        __nv_bfloat16 hi = __float2bfloat16_rn(v[j]);
        __nv_bfloat16 lo = __float2bfloat16_rn(v[j] - __bfloat162float(hi));
        if (ACT) { o[3*j] = hi; o[3*j+1] = lo; o[3*j+2] = hi; }
        else     { o[3*j] = hi; o[3*j+1] = hi; o[3*j+2] = lo; }
    }
    uint4* dst = (uint4*)(out + (size_t)i * 24);
    dst[0] = ((uint4*)o)[0];
    dst[1] = ((uint4*)o)[1];
    dst[2] = ((uint4*)o)[2];
}

// ---------------- tensor-core bf16 GEMM: C[M,N] = A3[M,K3] @ W3[N,K3]^T ----------------
// Tiles: BM=128, BN=128, BK=64. 256 threads = 8 warps, warp grid 2(M)x4(N), warp tile 64x32.
// Smem: double-buffered, rows of 128B with 16B-chunk XOR swizzle (c ^= row&7) ->
// conflict-free STS.128 and ldmatrix.
// MODE 0: scatter epilogue to g_q (scaled), g_k, g_v.  MODE 1: plain C store (N=4096).

__device__ __forceinline__ void ldsm_x4(uint32_t addr, uint32_t& r0, uint32_t& r1,
                                        uint32_t& r2, uint32_t& r3)
{
    asm volatile("ldmatrix.sync.aligned.m8n8.x4.shared.b16 {%0,%1,%2,%3}, [%4];"
                 : "=r"(r0), "=r"(r1), "=r"(r2), "=r"(r3) : "r"(addr));
}

__device__ __forceinline__ void mma_bf16(float* c, const uint32_t* a, const uint32_t* b)
{
    asm volatile("mma.sync.aligned.m16n8k16.row.col.f32.bf16.bf16.f32 "
                 "{%0,%1,%2,%3}, {%4,%5,%6,%7}, {%8,%9}, {%0,%1,%2,%3};"
                 : "+f"(c[0]), "+f"(c[1]), "+f"(c[2]), "+f"(c[3])
                 : "r"(a[0]), "r"(a[1]), "r"(a[2]), "r"(a[3]), "r"(b[0]), "r"(b[1]));
}

__device__ __forceinline__ void scatter_qkv(int m, int n, float val,
                                            float* __restrict__ q,
                                            float* __restrict__ k,
                                            float* __restrict__ v)
{
    const int bb = m >> 11;          // / T_
    const int t  = m & (T_ - 1);
    if (n < DIM_) {
        q[(((size_t)bb * NH + (n >> 7)) * T_ + t) * HD + (n & 127)] = val * QSCALE;
    } else {
        int cc = n - DIM_;
        const int d = cc & 127;
        if (cc < NKV * HD) {
            k[(((size_t)bb * NKV + (cc >> 7)) * T_ + t) * HD + d] = val;
        } else {
            cc -= NKV * HD;
            v[(((size_t)bb * NKV + (cc >> 7)) * T_ + t) * HD + d] = val;
        }
    }
}

template <int MODE>
__global__ void __launch_bounds__(256)
mma_gemm(const __nv_bfloat16* __restrict__ A,
         const __nv_bfloat16* __restrict__ W,
         float* __restrict__ outQ, float* __restrict__ outK, float* __restrict__ outV)
{
    extern __shared__ __align__(16) unsigned char smem[];   // 2 * (16KB A + 16KB B)

    const int tid  = threadIdx.x;
    const int lane = tid & 31;
    const int w    = tid >> 5;
    const int wm   = w & 1;          // 2 warps in M
    const int wn   = w >> 1;         // 4 warps in N
    const int m0   = blockIdx.y * 128;
    const int n0   = blockIdx.x * 128;

    // global->smem mapping: 128 rows x 8 chunks(16B); thread t -> row tid>>3 (+32u), chunk tid&7
    const int lr   = tid >> 3;
    const int lc   = tid & 7;
    const int sc16 = ((lc ^ (lr & 7)) << 4);   // swizzled chunk byte offset

    const __nv_bfloat16* Ag = A + (size_t)(m0 + lr) * K3 + lc * 8;
    const __nv_bfloat16* Wg = W + (size_t)(n0 + lr) * K3 + lc * 8;

    float acc[4][4][4];
#pragma unroll
    for (int i = 0; i < 4; i++)
#pragma unroll
        for (int j = 0; j < 4; j++)
#pragma unroll
            for (int e = 0; e < 4; e++) acc[i][j][e] = 0.f;

    // prologue loads
    uint4 pa[4], pb[4];
#pragma unroll
    for (int u = 0; u < 4; u++) {
        pa[u] = *(const uint4*)(Ag + (size_t)(32 * u) * K3);
        pb[u] = *(const uint4*)(Wg + (size_t)(32 * u) * K3);
    }

    // ldmatrix per-lane components
    const int rA  = lane & 15;             // A: row within 16-row frag
    const int cAh = lane >> 4;             // A: +0/+1 k-chunk (k+0 / k+8)
    const int rB  = (lane & 7) + ((lane >> 4) << 3);  // B: n row within 16-row pair
    const int cBh = (lane >> 3) & 1;       // B: k-chunk half

    for (int k0 = 0; k0 < K3; k0 += 64) {
        unsigned char* sa = smem + (((k0 >> 6) & 1) * 32768);
        unsigned char* sb = sa + 16384;

        // stage tiles (swizzled)
#pragma unroll
        for (int u = 0; u < 4; u++) {
            *(uint4*)(sa + (lr + 32 * u) * 128 + sc16) = pa[u];
            *(uint4*)(sb + (lr + 32 * u) * 128 + sc16) = pb[u];
        }
        __syncthreads();

        // prefetch next K-slab
        if (k0 + 64 < K3) {
#pragma unroll
            for (int u = 0; u < 4; u++) {
                pa[u] = *(const uint4*)(Ag + (size_t)(32 * u) * K3 + k0 + 64);
                pb[u] = *(const uint4*)(Wg + (size_t)(32 * u) * K3 + k0 + 64);
            }
        }

        const uint32_t saddr = (uint32_t)__cvta_generic_to_shared(sa);
        const uint32_t sbddr = saddr + 16384;

#pragma unroll
        for (int kk = 0; kk < 4; kk++) {
            uint32_t a[4][4], b[4][2];
#pragma unroll
            for (int mi = 0; mi < 4; mi++) {
                const int row = wm * 64 + mi * 16 + rA;
                const int ch  = kk * 2 + cAh;
                const uint32_t addr = saddr + row * 128 + ((ch ^ (row & 7)) << 4);
                ldsm_x4(addr, a[mi][0], a[mi][1], a[mi][2], a[mi][3]);
            }
#pragma unroll
            for (int np = 0; np < 2; np++) {   // two n-frag pairs -> 4 n-frags
                const int row = wn * 32 + np * 16 + rB;
                const int ch  = kk * 2 + cBh;
                const uint32_t addr = sbddr + row * 128 + ((ch ^ (row & 7)) << 4);
                uint32_t r0, r1, r2, r3;
                ldsm_x4(addr, r0, r1, r2, r3);
                b[np * 2][0] = r0; b[np * 2][1] = r1;
                b[np * 2 + 1][0] = r2; b[np * 2 + 1][1] = r3;
            }
#pragma unroll
            for (int mi = 0; mi < 4; mi++)
#pragma unroll
                for (int ni = 0; ni < 4; ni++)
                    mma_bf16(acc[mi][ni], a[mi], b[ni]);
        }
        // single barrier per iteration is sufficient with 2 stages:
        // STS(i+1) targets the buffer last read by compute(i-1), which every
        // warp finished before passing barrier(i).
    }

    // epilogue
    const int er = lane >> 2;
    const int ec = (lane & 3) * 2;
#pragma unroll
    for (int mi = 0; mi < 4; mi++) {
        const int m = m0 + wm * 64 + mi * 16 + er;
#pragma unroll
        for (int ni = 0; ni < 4; ni++) {
            const int n = n0 + wn * 32 + ni * 8 + ec;
            if (MODE == 1) {
                *(float2*)(outQ + (size_t)m * DIM_ + n)       = make_float2(acc[mi][ni][0], acc[mi][ni][1]);
                *(float2*)(outQ + (size_t)(m + 8) * DIM_ + n) = make_float2(acc[mi][ni][2], acc[mi][ni][3]);
            } else {
                scatter_qkv(m,     n,     acc[mi][ni][0], outQ, outK, outV);
                scatter_qkv(m,     n + 1, acc[mi][ni][1], outQ, outK, outV);
                scatter_qkv(m + 8, n,     acc[mi][ni][2], outQ, outK, outV);
                scatter_qkv(m + 8, n + 1, acc[mi][ni][3], outQ, outK, outV);
            }
        }
    }
}

// ---------------- flash attention, fp32, causal, GQA (unchanged) ----------------
#define BR 64
#define BC 64
#define FLASH_SMEM ((3 * BR * HD + BR * BC) * (int)sizeof(float))

__global__ void __launch_bounds__(256)
flash_kernel(const float* __restrict__ Q, const float* __restrict__ Kg,
             const float* __restrict__ Vg, float* __restrict__ O)
{
    extern __shared__ float sm[];
    float* Qs = sm;
    float* Ks = Qs + BR * HD;
    float* Vs = Ks + BC * HD;
    float* Ps = Vs + BC * HD;

    const int qt = blockIdx.x;
    const int h  = blockIdx.y;
    const int b  = blockIdx.z;
    const int g  = h / RG;
    const int tid = threadIdx.x;

    const float* Qbase = Q  + (((size_t)b * NH  + h) * T_ + (size_t)qt * BR) * HD;
    const float* Kbase = Kg + (((size_t)b * NKV + g) * T_) * HD;
    const float* Vbase = Vg + (((size_t)b * NKV + g) * T_) * HD;

    for (int i = tid; i < BR * HD / 4; i += 256)
        ((float4*)Qs)[i] = ((const float4*)Qbase)[i];

    const int r   = tid >> 2;
    const int c   = tid & 3;
    const int jj0 = c * 16;
    const int d0  = c * 32;

    float m_i = -1e30f, l_i = 0.f;
    float acc[32];
#pragma unroll
    for (int i = 0; i < 32; i++) acc[i] = 0.f;

    for (int kt = 0; kt <= qt; kt++) {
        __syncthreads();
        const float4* Ksrc = (const float4*)(Kbase + (size_t)kt * BC * HD);
        const float4* Vsrc = (const float4*)(Vbase + (size_t)kt * BC * HD);
        for (int i = tid; i < BC * HD / 4; i += 256) {
            ((float4*)Ks)[i] = Ksrc[i];
            ((float4*)Vs)[i] = Vsrc[i];
        }
        __syncthreads();

        float s[16];
#pragma unroll
        for (int j = 0; j < 16; j++) s[j] = 0.f;
        const float4* qrow = (const float4*)(Qs + r * HD);
#pragma unroll 4
        for (int d4 = 0; d4 < HD / 4; d4++) {
            float4 q4 = qrow[d4];
#pragma unroll
            for (int j = 0; j < 16; j++) {
                float4 k4 = ((const float4*)(Ks + (jj0 + j) * HD))[d4];
                s[j] += q4.x * k4.x + q4.y * k4.y + q4.z * k4.z + q4.w * k4.w;
            }
        }

        if (kt == qt) {
#pragma unroll
            for (int j = 0; j < 16; j++)
                if (jj0 + j > r) s[j] = -1e30f;
        }

        float mt = s[0];
#pragma unroll
        for (int j = 1; j < 16; j++) mt = fmaxf(mt, s[j]);
        mt = fmaxf(mt, __shfl_xor_sync(0xffffffffu, mt, 1));
        mt = fmaxf(mt, __shfl_xor_sync(0xffffffffu, mt, 2));
        const float mnew = fmaxf(m_i, mt);

        float lt = 0.f;
#pragma unroll
        for (int j = 0; j < 16; j++) {
            s[j] = __expf(s[j] - mnew);
            lt += s[j];
        }
        lt += __shfl_xor_sync(0xffffffffu, lt, 1);
        lt += __shfl_xor_sync(0xffffffffu, lt, 2);

        const float alpha = __expf(m_i - mnew);
        l_i = l_i * alpha + lt;
        m_i = mnew;
#pragma unroll
        for (int i = 0; i < 32; i++) acc[i] *= alpha;

#pragma unroll
        for (int j = 0; j < 16; j++) Ps[r * BC + jj0 + j] = s[j];
        __syncthreads();

#pragma unroll 4
        for (int j = 0; j < BC; j++) {
            const float p = Ps[r * BC + j];
            const float4* vrow = (const float4*)(Vs + j * HD + d0);
#pragma unroll
            for (int dd = 0; dd < 8; dd++) {
                float4 v4 = vrow[dd];
                acc[dd * 4 + 0] = fmaf(p, v4.x, acc[dd * 4 + 0]);
                acc[dd * 4 + 1] = fmaf(p, v4.y, acc[dd * 4 + 1]);
                acc[dd * 4 + 2] = fmaf(p, v4.z, acc[dd * 4 + 2]);
                acc[dd * 4 + 3] = fmaf(p, v4.w, acc[dd * 4 + 3]);
            }
        }
    }

    const float inv_l = 1.f / l_i;
    float* Od = O + ((size_t)(b * T_ + qt * BR + r)) * DIM_ + h * HD + d0;
#pragma unroll
    for (int dd = 0; dd < 8; dd++) {
        float4 o4;
        o4.x = acc[dd * 4 + 0] * inv_l;
        o4.y = acc[dd * 4 + 1] * inv_l;
        o4.z = acc[dd * 4 + 2] * inv_l;
        o4.w = acc[dd * 4 + 3] * inv_l;
        ((float4*)Od)[dd] = o4;
    }
}

// ---------------- launch ----------------
extern "C" void kernel_launch(void* const* d_in, const int* in_sizes, int n_in,
                              void* d_out, int out_size)
{
    const float* x   = (const float*)d_in[0];
    const float* Wq  = (const float*)d_in[1];
    const float* Wkv = (const float*)d_in[2];
    const float* Wo  = (const float*)d_in[3];
    float* out = (float*)d_out;

    float *pq, *pk, *pv, *po;
    __nv_bfloat16 *px3, *pw13, *po3, *pwo3;
    cudaGetSymbolAddress((void**)&pq,   g_q);
    cudaGetSymbolAddress((void**)&pk,   g_k);
    cudaGetSymbolAddress((void**)&pv,   g_v);
    cudaGetSymbolAddress((void**)&po,   g_o);
    cudaGetSymbolAddress((void**)&px3,  g_x3);
    cudaGetSymbolAddress((void**)&pw13, g_w13);
    cudaGetSymbolAddress((void**)&po3,  g_o3);
    cudaGetSymbolAddress((void**)&pwo3, g_wo3);

    cudaFuncSetAttribute(mma_gemm<0>, cudaFuncAttributeMaxDynamicSharedMemorySize, 65536);
    cudaFuncSetAttribute(mma_gemm<1>, cudaFuncAttributeMaxDynamicSharedMemorySize, 65536);
    cudaFuncSetAttribute(flash_kernel, cudaFuncAttributeMaxDynamicSharedMemorySize, FLASH_SMEM);

    const int n8_x  = (B_ * T_) * (DIM_ / 8);   // 4096*512
    const int n8_wq = DIM_ * (DIM_ / 8);
    const int n8_kv = (2 * NKV * HD) * (DIM_ / 8);

    // 0) expand operands to compensated bf16 triples
    conv3_kernel<true ><<<(n8_x  + 255) / 256, 256>>>(x,   px3, n8_x);
    conv3_kernel<false><<<(n8_wq + 255) / 256, 256>>>(Wq,  pw13, n8_wq);
    conv3_kernel<false><<<(n8_kv + 255) / 256, 256>>>(Wkv, pw13 + (size_t)DIM_ * K3, n8_kv);
    conv3_kernel<false><<<(n8_wq + 255) / 256, 256>>>(Wo,  pwo3, n8_wq);

    // 1) fused QKV projection on tensor cores: [4096,12288] @ [6144,12288]^T, scatter epilogue
    {
        dim3 grid((DIM_ + 2 * NKV * HD) / 128, (B_ * T_) / 128);   // 48 x 32
        mma_gemm<0><<<grid, 256, 65536>>>(px3, pw13, pq, pk, pv);
    }

    // 2) causal GQA flash attention (fp32)
    {
        dim3 grid(T_ / BR, NH, B_);
        flash_kernel<<<grid, 256, FLASH_SMEM>>>(pq, pk, pv, po);
    }

    // 3) output projection on tensor cores
    conv3_kernel<true><<<(n8_x + 255) / 256, 256>>>(po, po3, n8_x);
    {
        dim3 grid(DIM_ / 128, (B_ * T_) / 128);                    // 32 x 32
        mma_gemm<1><<<grid, 256, 65536>>>(po3, pwo3, out, nullptr, nullptr);
    }
}

// round 8
// speedup vs baseline: 6.7685x; 5.3242x over previous
#include <cuda_runtime.h>
#include <cuda_bf16.h>
#include <math.h>
#include <stdint.h>

#define B_   2
#define T_   2048
#define DIM_ 4096
#define NH   32
#define NKV  8
#define HD   128
#define RG   (NH / NKV)
#define K3   (3 * DIM_)          // 12288, triple-expanded K

#define QSCALE 0.08838834764831843f  // 1/sqrt(128)

typedef __nv_bfloat16 bf16;

// ---------------- scratch (allocation-free: __device__ globals) ----------------
__device__ float g_o[(size_t)B_ * T_ * DIM_];                   // attention out [B,T,H*hd]

// hi/lo split bf16 Q,K,V (written by QKV-GEMM epilogue)
__device__ bf16 g_qh[(size_t)B_ * NH  * T_ * HD];
__device__ bf16 g_ql[(size_t)B_ * NH  * T_ * HD];
__device__ bf16 g_kh[(size_t)B_ * NKV * T_ * HD];
__device__ bf16 g_kl[(size_t)B_ * NKV * T_ * HD];
__device__ bf16 g_vh[(size_t)B_ * NKV * T_ * HD];
__device__ bf16 g_vl[(size_t)B_ * NKV * T_ * HD];

// triple-expanded bf16 GEMM operands
__device__ bf16 g_x3 [(size_t)(B_*T_) * K3];
__device__ bf16 g_w13[(size_t)(DIM_ + 2*NKV*HD) * K3];
__device__ bf16 g_o3 [(size_t)(B_*T_) * K3];
__device__ bf16 g_wo3[(size_t)DIM_ * K3];

// ---------------- fp32 -> (hi,lo,hi)/(hi,hi,lo) bf16 expansion ----------------
template <bool ACT>
__global__ void __launch_bounds__(256)
conv3_kernel(const float* __restrict__ in, bf16* __restrict__ out, int n8)
{
    int i = blockIdx.x * blockDim.x + threadIdx.x;
    if (i >= n8) return;
    float4 f0 = ((const float4*)in)[(size_t)i * 2];
    float4 f1 = ((const float4*)in)[(size_t)i * 2 + 1];
    float v[8] = {f0.x, f0.y, f0.z, f0.w, f1.x, f1.y, f1.z, f1.w};
    __align__(16) bf16 o[24];
#pragma unroll
    for (int j = 0; j < 8; j++) {
        bf16 hi = __float2bfloat16_rn(v[j]);
        bf16 lo = __float2bfloat16_rn(v[j] - __bfloat162float(hi));
        if (ACT) { o[3*j] = hi; o[3*j+1] = lo; o[3*j+2] = hi; }
        else     { o[3*j] = hi; o[3*j+1] = hi; o[3*j+2] = lo; }
    }
    uint4* dst = (uint4*)(out + (size_t)i * 24);
    dst[0] = ((uint4*)o)[0];
    dst[1] = ((uint4*)o)[1];
    dst[2] = ((uint4*)o)[2];
}

// ---------------- mma helpers ----------------
__device__ __forceinline__ void ldsm_x4(uint32_t addr, uint32_t& r0, uint32_t& r1,
                                        uint32_t& r2, uint32_t& r3)
{
    asm volatile("ldmatrix.sync.aligned.m8n8.x4.shared.b16 {%0,%1,%2,%3}, [%4];"
                 : "=r"(r0), "=r"(r1), "=r"(r2), "=r"(r3) : "r"(addr));
}
__device__ __forceinline__ void ldsm_x4_t(uint32_t addr, uint32_t& r0, uint32_t& r1,
                                          uint32_t& r2, uint32_t& r3)
{
    asm volatile("ldmatrix.sync.aligned.m8n8.x4.trans.shared.b16 {%0,%1,%2,%3}, [%4];"
                 : "=r"(r0), "=r"(r1), "=r"(r2), "=r"(r3) : "r"(addr));
}
__device__ __forceinline__ void mma_bf16(float* c, const uint32_t* a, const uint32_t* b)
{
    asm volatile("mma.sync.aligned.m16n8k16.row.col.f32.bf16.bf16.f32 "
                 "{%0,%1,%2,%3}, {%4,%5,%6,%7}, {%8,%9}, {%0,%1,%2,%3};"
                 : "+f"(c[0]), "+f"(c[1]), "+f"(c[2]), "+f"(c[3])
                 : "r"(a[0]), "r"(a[1]), "r"(a[2]), "r"(a[3]), "r"(b[0]), "r"(b[1]));
}
__device__ __forceinline__ uint32_t pk2(float a, float b)
{
    __nv_bfloat162 t; t.x = __float2bfloat16_rn(a); t.y = __float2bfloat16_rn(b);
    return *reinterpret_cast<uint32_t*>(&t);
}

// ---------------- scatter epilogue: fp32 -> hi/lo bf16 Q/K/V ----------------
__device__ __forceinline__ void store_hl(bf16* __restrict__ hi, bf16* __restrict__ lo,
                                         size_t idx, float v0, float v1)
{
    bf16 h0 = __float2bfloat16_rn(v0), h1 = __float2bfloat16_rn(v1);
    bf16 e0 = __float2bfloat16_rn(v0 - __bfloat162float(h0));
    bf16 e1 = __float2bfloat16_rn(v1 - __bfloat162float(h1));
    __nv_bfloat162 H; H.x = h0; H.y = h1;
    __nv_bfloat162 L; L.x = e0; L.y = e1;
    *(__nv_bfloat162*)(hi + idx) = H;
    *(__nv_bfloat162*)(lo + idx) = L;
}

__device__ __forceinline__ void scatter2(int m, int n, float v0, float v1,
                                         bf16* qh, bf16* ql, bf16* kh, bf16* kl,
                                         bf16* vh, bf16* vl)
{
    const int bb = m >> 11;
    const int t  = m & (T_ - 1);
    if (n < DIM_) {
        size_t idx = (((size_t)bb * NH + (n >> 7)) * T_ + t) * HD + (n & 127);
        store_hl(qh, ql, idx, v0 * QSCALE, v1 * QSCALE);
    } else {
        int cc = n - DIM_;
        if (cc < NKV * HD) {
            size_t idx = (((size_t)bb * NKV + (cc >> 7)) * T_ + t) * HD + (cc & 127);
            store_hl(kh, kl, idx, v0, v1);
        } else {
            cc -= NKV * HD;
            size_t idx = (((size_t)bb * NKV + (cc >> 7)) * T_ + t) * HD + (cc & 127);
            store_hl(vh, vl, idx, v0, v1);
        }
    }
}

// ---------------- tensor-core bf16 GEMM: C[M,N] = A3[M,K3] @ W3[N,K3]^T ----------------
template <int MODE>
__global__ void __launch_bounds__(256)
mma_gemm(const bf16* __restrict__ A, const bf16* __restrict__ W,
         float* __restrict__ outC,
         bf16* qh, bf16* ql, bf16* kh, bf16* kl, bf16* vh, bf16* vl)
{
    extern __shared__ __align__(16) unsigned char smem[];   // 2 * (16KB A + 16KB B)

    const int tid  = threadIdx.x;
    const int lane = tid & 31;
    const int w    = tid >> 5;
    const int wm   = w & 1;
    const int wn   = w >> 1;
    const int m0   = blockIdx.y * 128;
    const int n0   = blockIdx.x * 128;

    const int lr   = tid >> 3;
    const int lc   = tid & 7;
    const int sc16 = ((lc ^ (lr & 7)) << 4);

    const bf16* Ag = A + (size_t)(m0 + lr) * K3 + lc * 8;
    const bf16* Wg = W + (size_t)(n0 + lr) * K3 + lc * 8;

    float acc[4][4][4];
#pragma unroll
    for (int i = 0; i < 4; i++)
#pragma unroll
        for (int j = 0; j < 4; j++)
#pragma unroll
            for (int e = 0; e < 4; e++) acc[i][j][e] = 0.f;

    uint4 pa[4], pb[4];
#pragma unroll
    for (int u = 0; u < 4; u++) {
        pa[u] = *(const uint4*)(Ag + (size_t)(32 * u) * K3);
        pb[u] = *(const uint4*)(Wg + (size_t)(32 * u) * K3);
    }

    const int rA  = lane & 15;
    const int cAh = lane >> 4;
    const int rB  = (lane & 7) + ((lane >> 4) << 3);
    const int cBh = (lane >> 3) & 1;

    for (int k0 = 0; k0 < K3; k0 += 64) {
        unsigned char* sa = smem + (((k0 >> 6) & 1) * 32768);
        unsigned char* sb = sa + 16384;

#pragma unroll
        for (int u = 0; u < 4; u++) {
            *(uint4*)(sa + (lr + 32 * u) * 128 + sc16) = pa[u];
            *(uint4*)(sb + (lr + 32 * u) * 128 + sc16) = pb[u];
        }
        __syncthreads();

        if (k0 + 64 < K3) {
#pragma unroll
            for (int u = 0; u < 4; u++) {
                pa[u] = *(const uint4*)(Ag + (size_t)(32 * u) * K3 + k0 + 64);
                pb[u] = *(const uint4*)(Wg + (size_t)(32 * u) * K3 + k0 + 64);
            }
        }

        const uint32_t saddr = (uint32_t)__cvta_generic_to_shared(sa);
        const uint32_t sbddr = saddr + 16384;

#pragma unroll
        for (int kk = 0; kk < 4; kk++) {
            uint32_t a[4][4], b[4][2];
#pragma unroll
            for (int mi = 0; mi < 4; mi++) {
                const int row = wm * 64 + mi * 16 + rA;
                const int ch  = kk * 2 + cAh;
                const uint32_t addr = saddr + row * 128 + ((ch ^ (row & 7)) << 4);
                ldsm_x4(addr, a[mi][0], a[mi][1], a[mi][2], a[mi][3]);
            }
#pragma unroll
            for (int np = 0; np < 2; np++) {
                const int row = wn * 32 + np * 16 + rB;
                const int ch  = kk * 2 + cBh;
                const uint32_t addr = sbddr + row * 128 + ((ch ^ (row & 7)) << 4);
                uint32_t r0, r1, r2, r3;
                ldsm_x4(addr, r0, r1, r2, r3);
                b[np * 2][0] = r0; b[np * 2][1] = r1;
                b[np * 2 + 1][0] = r2; b[np * 2 + 1][1] = r3;
            }
#pragma unroll
            for (int mi = 0; mi < 4; mi++)
#pragma unroll
                for (int ni = 0; ni < 4; ni++)
                    mma_bf16(acc[mi][ni], a[mi], b[ni]);
        }
    }

    const int er = lane >> 2;
    const int ec = (lane & 3) * 2;
#pragma unroll
    for (int mi = 0; mi < 4; mi++) {
        const int m = m0 + wm * 64 + mi * 16 + er;
#pragma unroll
        for (int ni = 0; ni < 4; ni++) {
            const int n = n0 + wn * 32 + ni * 8 + ec;
            if (MODE == 1) {
                *(float2*)(outC + (size_t)m * DIM_ + n)       = make_float2(acc[mi][ni][0], acc[mi][ni][1]);
                *(float2*)(outC + (size_t)(m + 8) * DIM_ + n) = make_float2(acc[mi][ni][2], acc[mi][ni][3]);
            } else {
                scatter2(m,     n, acc[mi][ni][0], acc[mi][ni][1], qh, ql, kh, kl, vh, vl);
                scatter2(m + 8, n, acc[mi][ni][2], acc[mi][ni][3], qh, ql, kh, kl, vh, vl);
            }
        }
    }
}

// ---------------- tensor-core flash attention (compensated bf16) ----------------
// Br=128 (8 warps x 16 rows), Bc=64, hd=128.
// S = qh*kh + ql*kh + qh*kl ; O += ph*vh + pl*vh + ph*vl
// smem: Qh 32K | Ql 32K | Kh 16K | Kl 16K | Vh 16K | Vl 16K = 128KB
#define FL_SMEM 131072

__global__ void __launch_bounds__(256)
flash_mma(const bf16* __restrict__ Qh, const bf16* __restrict__ Ql,
          const bf16* __restrict__ Kh, const bf16* __restrict__ Kl,
          const bf16* __restrict__ Vh, const bf16* __restrict__ Vl,
          float* __restrict__ O)
{
    extern __shared__ __align__(16) unsigned char sm[];
    const uint32_t sb  = (uint32_t)__cvta_generic_to_shared(sm);
    const uint32_t bQh = sb, bQl = sb + 32768;
    const uint32_t bKh = sb + 65536, bKl = sb + 81920;
    const uint32_t bVh = sb + 98304, bVl = sb + 114688;

    const int qt = blockIdx.x, h = blockIdx.y, b = blockIdx.z;
    const int g  = h / RG;
    const int tid = threadIdx.x, lane = tid & 31, wr = tid >> 5;

    // ---- load Q tile (hi+lo), swizzled rows of 256B / 16 chunks ----
    {
        const bf16* qhg = Qh + (((size_t)b * NH + h) * T_ + (size_t)qt * 128) * HD;
        const bf16* qlg = Ql + (((size_t)b * NH + h) * T_ + (size_t)qt * 128) * HD;
#pragma unroll
        for (int u = 0; u < 8; u++) {
            const int s = tid + 256 * u;
            const int row = s >> 4, ch = s & 15;
            const int so = row * 256 + ((ch ^ (row & 7)) << 4);
            const int go = row * HD + ch * 8;
            *(uint4*)(sm + so)         = *(const uint4*)(qhg + go);
            *(uint4*)(sm + 32768 + so) = *(const uint4*)(qlg + go);
        }
    }

    float oacc[16][4];
#pragma unroll
    for (int i = 0; i < 16; i++)
#pragma unroll
        for (int e = 0; e < 4; e++) oacc[i][e] = 0.f;
    float m0 = -1e30f, m1 = -1e30f, l0 = 0.f, l1 = 0.f;

    // per-lane ldmatrix geometry
    const int arow = wr * 16 + (lane & 15);
    const int axh  = lane >> 4;                         // A k-chunk half
    const int bxh  = (lane >> 3) & 1;                   // B k-chunk half
    const int brow_base = (lane & 7) + ((lane >> 4) << 3);
    const int rowg0 = qt * 128 + wr * 16 + (lane >> 2);

    const bf16* khg = Kh + (((size_t)b * NKV + g) * T_) * HD;
    const bf16* klg = Kl + (((size_t)b * NKV + g) * T_) * HD;
    const bf16* vhg = Vh + (((size_t)b * NKV + g) * T_) * HD;
    const bf16* vlg = Vl + (((size_t)b * NKV + g) * T_) * HD;

    const int ktmax = 2 * qt + 1;
    for (int kt = 0; kt <= ktmax; kt++) {
        __syncthreads();
        // ---- stage K,V (hi+lo), 64 rows ----
        {
            const size_t base = (size_t)kt * 64 * HD;
#pragma unroll
            for (int u = 0; u < 4; u++) {
                const int s = tid + 256 * u;
                const int row = s >> 4, ch = s & 15;
                const int so = row * 256 + ((ch ^ (row & 7)) << 4);
                const size_t go = base + row * HD + ch * 8;
                *(uint4*)(sm + 65536  + so) = *(const uint4*)(khg + go);
                *(uint4*)(sm + 81920  + so) = *(const uint4*)(klg + go);
                *(uint4*)(sm + 98304  + so) = *(const uint4*)(vhg + go);
                *(uint4*)(sm + 114688 + so) = *(const uint4*)(vlg + go);
            }
        }
        __syncthreads();

        // fully-masked warp? (min col > max row of this warp's 16 rows)
        if (kt * 64 > qt * 128 + wr * 16 + 15) continue;

        // ---- S = Q K^T (3 compensated passes) ----
        float s[8][4];
#pragma unroll
        for (int nf = 0; nf < 8; nf++)
#pragma unroll
            for (int e = 0; e < 4; e++) s[nf][e] = 0.f;

#pragma unroll
        for (int kk = 0; kk < 8; kk++) {
            uint32_t qhf[4], qlf[4], bh[8][2], bl[8][2];
            {
                const int ch = kk * 2 + axh;
                const uint32_t sw = arow * 256 + ((ch ^ (arow & 7)) << 4);
                ldsm_x4(bQh + sw, qhf[0], qhf[1], qhf[2], qhf[3]);
                ldsm_x4(bQl + sw, qlf[0], qlf[1], qlf[2], qlf[3]);
            }
#pragma unroll
            for (int p = 0; p < 4; p++) {
                const int row = p * 16 + brow_base;
                const int ch  = kk * 2 + bxh;
                const uint32_t sw = row * 256 + ((ch ^ (row & 7)) << 4);
                uint32_t r0, r1, r2, r3;
                ldsm_x4(bKh + sw, r0, r1, r2, r3);
                bh[p*2][0] = r0; bh[p*2][1] = r1; bh[p*2+1][0] = r2; bh[p*2+1][1] = r3;
                ldsm_x4(bKl + sw, r0, r1, r2, r3);
                bl[p*2][0] = r0; bl[p*2][1] = r1; bl[p*2+1][0] = r2; bl[p*2+1][1] = r3;
            }
#pragma unroll
            for (int nf = 0; nf < 8; nf++) {
                mma_bf16(s[nf], qhf, bh[nf]);
                mma_bf16(s[nf], qlf, bh[nf]);
                mma_bf16(s[nf], qhf, bl[nf]);
            }
        }

        // ---- causal mask (only tiles overlapping the diagonal) ----
        if (kt * 64 + 63 > rowg0) {
            const int rowg1 = rowg0 + 8;
#pragma unroll
            for (int nf = 0; nf < 8; nf++) {
                const int c = kt * 64 + nf * 8 + (lane & 3) * 2;
                if (c     > rowg0) s[nf][0] = -1e30f;
                if (c + 1 > rowg0) s[nf][1] = -1e30f;
                if (c     > rowg1) s[nf][2] = -1e30f;
                if (c + 1 > rowg1) s[nf][3] = -1e30f;
            }
        }

        // ---- online softmax (rows r and r+8, quad reductions) ----
        float mt0 = s[0][0], mt1 = s[0][2];
#pragma unroll
        for (int nf = 0; nf < 8; nf++) {
            mt0 = fmaxf(mt0, fmaxf(s[nf][0], s[nf][1]));
            mt1 = fmaxf(mt1, fmaxf(s[nf][2], s[nf][3]));
        }
        mt0 = fmaxf(mt0, __shfl_xor_sync(0xffffffffu, mt0, 1));
        mt0 = fmaxf(mt0, __shfl_xor_sync(0xffffffffu, mt0, 2));
        mt1 = fmaxf(mt1, __shfl_xor_sync(0xffffffffu, mt1, 1));
        mt1 = fmaxf(mt1, __shfl_xor_sync(0xffffffffu, mt1, 2));
        const float mn0 = fmaxf(m0, mt0), mn1 = fmaxf(m1, mt1);

        float lt0 = 0.f, lt1 = 0.f;
#pragma unroll
        for (int nf = 0; nf < 8; nf++) {
            s[nf][0] = __expf(s[nf][0] - mn0); lt0 += s[nf][0];
            s[nf][1] = __expf(s[nf][1] - mn0); lt0 += s[nf][1];
            s[nf][2] = __expf(s[nf][2] - mn1); lt1 += s[nf][2];
            s[nf][3] = __expf(s[nf][3] - mn1); lt1 += s[nf][3];
        }
        lt0 += __shfl_xor_sync(0xffffffffu, lt0, 1);
        lt0 += __shfl_xor_sync(0xffffffffu, lt0, 2);
        lt1 += __shfl_xor_sync(0xffffffffu, lt1, 1);
        lt1 += __shfl_xor_sync(0xffffffffu, lt1, 2);

        const float al0 = __expf(m0 - mn0), al1 = __expf(m1 - mn1);
        m0 = mn0; m1 = mn1;
        l0 = l0 * al0 + lt0; l1 = l1 * al1 + lt1;
#pragma unroll
        for (int i = 0; i < 16; i++) {
            oacc[i][0] *= al0; oacc[i][1] *= al0;
            oacc[i][2] *= al1; oacc[i][3] *= al1;
        }

        // ---- repack P (C-layout == A-layout) into hi/lo A-fragments ----
        uint32_t pha[4][4], pla[4][4];
#pragma unroll
        for (int kc = 0; kc < 4; kc++) {
            const float* c0 = s[2*kc];
            const float* c1 = s[2*kc + 1];
            float h00 = __bfloat162float(__float2bfloat16_rn(c0[0]));
            float h01 = __bfloat162float(__float2bfloat16_rn(c0[1]));
            float h02 = __bfloat162float(__float2bfloat16_rn(c0[2]));
            float h03 = __bfloat162float(__float2bfloat16_rn(c0[3]));
            float h10 = __bfloat162float(__float2bfloat16_rn(c1[0]));
            float h11 = __bfloat162float(__float2bfloat16_rn(c1[1]));
            float h12 = __bfloat162float(__float2bfloat16_rn(c1[2]));
            float h13 = __bfloat162float(__float2bfloat16_rn(c1[3]));
            pha[kc][0] = pk2(c0[0], c0[1]);   pha[kc][1] = pk2(c0[2], c0[3]);
            pha[kc][2] = pk2(c1[0], c1[1]);   pha[kc][3] = pk2(c1[2], c1[3]);
            pla[kc][0] = pk2(c0[0]-h00, c0[1]-h01);
            pla[kc][1] = pk2(c0[2]-h02, c0[3]-h03);
            pla[kc][2] = pk2(c1[0]-h10, c1[1]-h11);
            pla[kc][3] = pk2(c1[2]-h12, c1[3]-h13);
        }

        // ---- O += P V (3 compensated passes), V via ldmatrix.trans ----
#pragma unroll
        for (int kc = 0; kc < 4; kc++) {
            const int krow = kc * 16 + (lane & 15);
            const uint32_t rbase = krow * 256;
            const int rxor = krow & 7;
#pragma unroll
            for (int hf = 0; hf < 2; hf++) {
                uint32_t vh[8][2], vl[8][2];
#pragma unroll
                for (int q4 = 0; q4 < 4; q4++) {
                    const int ch = hf * 8 + q4 * 2 + axh;
                    const uint32_t sw = rbase + ((ch ^ rxor) << 4);
                    uint32_t r0, r1, r2, r3;
                    ldsm_x4_t(bVh + sw, r0, r1, r2, r3);
                    vh[q4*2][0] = r0; vh[q4*2][1] = r1; vh[q4*2+1][0] = r2; vh[q4*2+1][1] = r3;
                    ldsm_x4_t(bVl + sw, r0, r1, r2, r3);
                    vl[q4*2][0] = r0; vl[q4*2][1] = r1; vl[q4*2+1][0] = r2; vl[q4*2+1][1] = r3;
                }
#pragma unroll
                for (int j = 0; j < 8; j++) {
                    const int nf2 = hf * 8 + j;
                    mma_bf16(oacc[nf2], pha[kc], vh[j]);
                    mma_bf16(oacc[nf2], pla[kc], vh[j]);
                    mma_bf16(oacc[nf2], pha[kc], vl[j]);
                }
            }
        }
    }

    // ---- epilogue: O / l -> g_o [B,T,H*hd] ----
    const float il0 = 1.f / l0, il1 = 1.f / l1;
    const int row = qt * 128 + wr * 16 + (lane >> 2);
    float* o0 = O + ((size_t)b * T_ + row) * DIM_ + h * HD + (lane & 3) * 2;
    float* o1 = o0 + 8 * DIM_;
#pragma unroll
    for (int nf2 = 0; nf2 < 16; nf2++) {
        *(float2*)(o0 + nf2 * 8) = make_float2(oacc[nf2][0] * il0, oacc[nf2][1] * il0);
        *(float2*)(o1 + nf2 * 8) = make_float2(oacc[nf2][2] * il1, oacc[nf2][3] * il1);
    }
}

// ---------------- launch ----------------
extern "C" void kernel_launch(void* const* d_in, const int* in_sizes, int n_in,
                              void* d_out, int out_size)
{
    const float* x   = (const float*)d_in[0];
    const float* Wq  = (const float*)d_in[1];
    const float* Wkv = (const float*)d_in[2];
    const float* Wo  = (const float*)d_in[3];
    float* out = (float*)d_out;

    float* po;
    bf16 *pqh, *pql, *pkh, *pkl, *pvh, *pvl, *px3, *pw13, *po3, *pwo3;
    cudaGetSymbolAddress((void**)&po,   g_o);
    cudaGetSymbolAddress((void**)&pqh,  g_qh);
    cudaGetSymbolAddress((void**)&pql,  g_ql);
    cudaGetSymbolAddress((void**)&pkh,  g_kh);
    cudaGetSymbolAddress((void**)&pkl,  g_kl);
    cudaGetSymbolAddress((void**)&pvh,  g_vh);
    cudaGetSymbolAddress((void**)&pvl,  g_vl);
    cudaGetSymbolAddress((void**)&px3,  g_x3);
    cudaGetSymbolAddress((void**)&pw13, g_w13);
    cudaGetSymbolAddress((void**)&po3,  g_o3);
    cudaGetSymbolAddress((void**)&pwo3, g_wo3);

    cudaFuncSetAttribute(mma_gemm<0>, cudaFuncAttributeMaxDynamicSharedMemorySize, 65536);
    cudaFuncSetAttribute(mma_gemm<1>, cudaFuncAttributeMaxDynamicSharedMemorySize, 65536);
    cudaFuncSetAttribute(flash_mma,   cudaFuncAttributeMaxDynamicSharedMemorySize, FL_SMEM);

    const int n8_x  = (B_ * T_) * (DIM_ / 8);
    const int n8_wq = DIM_ * (DIM_ / 8);
    const int n8_kv = (2 * NKV * HD) * (DIM_ / 8);

    // 0) expand operands to compensated bf16 triples
    conv3_kernel<true ><<<(n8_x  + 255) / 256, 256>>>(x,   px3, n8_x);
    conv3_kernel<false><<<(n8_wq + 255) / 256, 256>>>(Wq,  pw13, n8_wq);
    conv3_kernel<false><<<(n8_kv + 255) / 256, 256>>>(Wkv, pw13 + (size_t)DIM_ * K3, n8_kv);
    conv3_kernel<false><<<(n8_wq + 255) / 256, 256>>>(Wo,  pwo3, n8_wq);

    // 1) fused QKV projection (tensor cores), hi/lo bf16 scatter epilogue
    {
        dim3 grid((DIM_ + 2 * NKV * HD) / 128, (B_ * T_) / 128);   // 48 x 32
        mma_gemm<0><<<grid, 256, 65536>>>(px3, pw13, nullptr, pqh, pql, pkh, pkl, pvh, pvl);
    }

    // 2) causal GQA flash attention on tensor cores
    {
        dim3 grid(T_ / 128, NH, B_);   // 16 x 32 x 2
        flash_mma<<<grid, 256, FL_SMEM>>>(pqh, pql, pkh, pkl, pvh, pvl, po);
    }

    // 3) output projection (tensor cores)
    conv3_kernel<true><<<(n8_x + 255) / 256, 256>>>(po, po3, n8_x);
    {
        dim3 grid(DIM_ / 128, (B_ * T_) / 128);                    // 32 x 32
        mma_gemm<1><<<grid, 256, 65536>>>(po3, pwo3, out, nullptr, nullptr, nullptr, nullptr, nullptr, nullptr);
    }
}